// round 10
// baseline (speedup 1.0000x reference)
#include <cuda_runtime.h>

// Problem constants (fixed shapes per reference)
#define BB   16
#define NN   1024
#define D2H  1024
#define UU   512
#define BN   (BB * NN)      // 16384 rows

// Scratch (device globals; no allocation allowed)
__device__ float g_v[2 * D2H];        // [0:1024)=v_h, [1024:2048)=v_m
__device__ float g_c[2];              // c_h + b_out, c_m
__device__ float g_sM[BN];            // modifier scores (cross-block)
__device__ unsigned g_cnt[BB];        // per-batch completion counters

// ---------------------------------------------------------------------------
// Kernel 1: fold the output layer into input space, one kernel.
//   v_h[d] = sum_u W_h[u,d]*w_out[u] ; v_m likewise ; c_h = w_out.b_h + b_out
// Grid: 32 blocks x 256 threads. Block g owns d in [32g, 32g+32); its 8 warps
// split u into 64-chunks (128 coalesced 128B-line loads per thread), then a
// smem cross-warp reduction. Also zeroes the batch counters for kernel 2.
// ---------------------------------------------------------------------------
__global__ void fold_kernel(const float* __restrict__ W_h,
                            const float* __restrict__ b_h,
                            const float* __restrict__ W_m,
                            const float* __restrict__ b_m,
                            const float* __restrict__ w_out,
                            const float* __restrict__ b_out) {
    __shared__ float sw[UU];
    __shared__ float ph[8][32], pm[8][32];
    int tid  = threadIdx.x;
    int warp = tid >> 5, lane = tid & 31;

    for (int i = tid; i < UU; i += 256) sw[i] = w_out[i];
    if (blockIdx.x == 0 && tid < BB) g_cnt[tid] = 0;   // reset for kernel 2
    __syncthreads();

    int d = blockIdx.x * 32 + lane;
    float vh = 0.f, vm = 0.f;
#pragma unroll 8
    for (int k = 0; k < 64; k++) {
        int u = warp * 64 + k;
        float w = sw[u];
        vh = fmaf(W_h[u * D2H + d], w, vh);
        vm = fmaf(W_m[u * D2H + d], w, vm);
    }
    ph[warp][lane] = vh;
    pm[warp][lane] = vm;
    __syncthreads();

    if (warp == 0) {
        float a = 0.f;
#pragma unroll
        for (int w = 0; w < 8; w++) a += ph[w][lane];
        g_v[blockIdx.x * 32 + lane] = a;
    } else if (warp == 1) {
        float a = 0.f;
#pragma unroll
        for (int w = 0; w < 8; w++) a += pm[w][lane];
        g_v[D2H + blockIdx.x * 32 + lane] = a;
    } else if (blockIdx.x == 0 && warp == 2) {
        float ch = 0.f, cm = 0.f;
        for (int u = lane; u < UU; u += 32) {
            ch = fmaf(b_h[u], sw[u], ch);
            cm = fmaf(b_m[u], sw[u], cm);
        }
#pragma unroll
        for (int o = 16; o > 0; o >>= 1) {
            ch += __shfl_down_sync(0xffffffffu, ch, o);
            cm += __shfl_down_sync(0xffffffffu, cm, o);
        }
        if (lane == 0) {
            g_c[0] = ch + b_out[0];
            g_c[1] = cm;
        }
    }
}

// ---------------------------------------------------------------------------
// Kernel 2: fused dots + broadcast.
// Phase A (dots): block handles 8 rows (2 per warp, 16 outstanding float4
//   loads/lane); sH kept in smem, sM published to global with release fence
//   + per-batch counter.
// Phase B (bcast): spin until all 128 blocks of this batch published sM,
//   then write out[b,i,j] = sH[i] + sM[b,j] for the same 8 rows.
// Early batches' output writes overlap later batches' x reads.
// Grid: 2048 blocks x 256 threads.
// ---------------------------------------------------------------------------
__global__ void fused_kernel(const float* __restrict__ x,
                             float* __restrict__ out) {
    __shared__ float4 sv[2 * D2H / 4];   // 8 KB: v_h then v_m
    __shared__ float  ssH[8];
    int tid = threadIdx.x;
    const float4* gv4 = (const float4*)g_v;
    for (int i = tid; i < 2 * D2H / 4; i += 256) sv[i] = gv4[i];
    __syncthreads();

    int warp = tid >> 5, lane = tid & 31;
    int bi0  = blockIdx.x * 8;           // this block's 8 rows
    int b    = blockIdx.x >> 7;          // batch (128 blocks per batch)
    int row0 = bi0 + warp * 2;

    // ---- Phase A: dots for rows row0, row0+1 ----
    const float4* xa = (const float4*)(x + (size_t)row0 * D2H);
    const float4* xb = xa + (D2H / 4);
    float ah0 = 0.f, am0 = 0.f, ah1 = 0.f, am1 = 0.f;
#pragma unroll
    for (int k = 0; k < 8; k++) {
        int i = k * 32 + lane;
        float4 va = xa[i];
        float4 vb = xb[i];
        float4 h  = sv[i];
        float4 m  = sv[256 + i];
        ah0 = fmaf(va.x, h.x, fmaf(va.y, h.y, fmaf(va.z, h.z, fmaf(va.w, h.w, ah0))));
        am0 = fmaf(va.x, m.x, fmaf(va.y, m.y, fmaf(va.z, m.z, fmaf(va.w, m.w, am0))));
        ah1 = fmaf(vb.x, h.x, fmaf(vb.y, h.y, fmaf(vb.z, h.z, fmaf(vb.w, h.w, ah1))));
        am1 = fmaf(vb.x, m.x, fmaf(vb.y, m.y, fmaf(vb.z, m.z, fmaf(vb.w, m.w, am1))));
    }
#pragma unroll
    for (int o = 16; o > 0; o >>= 1) {
        ah0 += __shfl_down_sync(0xffffffffu, ah0, o);
        am0 += __shfl_down_sync(0xffffffffu, am0, o);
        ah1 += __shfl_down_sync(0xffffffffu, ah1, o);
        am1 += __shfl_down_sync(0xffffffffu, am1, o);
    }
    if (lane == 0) {
        float ch = g_c[0], cm = g_c[1];
        ssH[warp * 2]     = ah0 + ch;    // sH stays block-local in smem
        ssH[warp * 2 + 1] = ah1 + ch;
        g_sM[row0]     = am0 + cm;       // sM is needed cross-block
        g_sM[row0 + 1] = am1 + cm;
        __threadfence();                 // release our sM stores
    }
    __syncthreads();                     // all warps' fences done

    // ---- publish + wait for whole batch ----
    if (tid == 0) {
        atomicAdd(&g_cnt[b], 1u);
        volatile unsigned* p = &g_cnt[b];
        while (*p < 128u) __nanosleep(64);
    }
    __syncthreads();
    __threadfence();                     // acquire published sM

    // ---- Phase B: broadcast-add this block's 8 rows ----
    const float4* m4 = (const float4*)g_sM + b * (NN / 4);
    float4 m = m4[tid];

    float s[8];
#pragma unroll
    for (int r = 0; r < 8; r++) s[r] = ssH[r];

    float4* o4 = (float4*)out + (size_t)bi0 * (NN / 4) + tid;
#pragma unroll
    for (int r = 0; r < 8; r++) {
        o4[r * (NN / 4)] = make_float4(s[r] + m.x, s[r] + m.y,
                                       s[r] + m.z, s[r] + m.w);
    }
}

// ---------------------------------------------------------------------------
extern "C" void kernel_launch(void* const* d_in, const int* in_sizes, int n_in,
                              void* d_out, int out_size) {
    const float* x     = (const float*)d_in[0];
    const float* W_h   = (const float*)d_in[1];
    const float* b_h   = (const float*)d_in[2];
    const float* W_m   = (const float*)d_in[3];
    const float* b_m   = (const float*)d_in[4];
    const float* w_out = (const float*)d_in[5];
    const float* b_out = (const float*)d_in[6];
    float* out = (float*)d_out;

    fold_kernel<<<32, 256>>>(W_h, b_h, W_m, b_m, w_out, b_out);
    fused_kernel<<<BN / 8, 256>>>(x, out);
}

// round 11
// speedup vs baseline: 1.2711x; 1.2711x over previous
#include <cuda_runtime.h>

// Problem constants (fixed shapes per reference)
#define BB   16
#define NN   1024
#define D2H  1024
#define UU   512
#define BN   (BB * NN)      // 16384 rows

// Scratch (device globals; no allocation allowed)
__device__ float g_v[2 * D2H];        // [0:1024)=v_h, [1024:2048)=v_m
__device__ float g_c[2];              // c_h + b_out, c_m
__device__ float g_sH[BN];
__device__ float g_sM[BN];

// ---------------------------------------------------------------------------
// Kernel 1: fold the output layer into input space (single launch).
//   v_h[d] = sum_u W_h[u,d]*w_out[u] ; v_m likewise ; c_h = w_out.b_h + b_out
// Grid: 32 blocks x 256 threads. Block g owns d in [32g, 32g+32); its 8 warps
// split u into 64-chunks (128 coalesced 128B-line loads per thread), then a
// smem cross-warp reduction.
// ---------------------------------------------------------------------------
__global__ void fold_kernel(const float* __restrict__ W_h,
                            const float* __restrict__ b_h,
                            const float* __restrict__ W_m,
                            const float* __restrict__ b_m,
                            const float* __restrict__ w_out,
                            const float* __restrict__ b_out) {
    __shared__ float sw[UU];
    __shared__ float ph[8][32], pm[8][32];
    int tid  = threadIdx.x;
    int warp = tid >> 5, lane = tid & 31;

    for (int i = tid; i < UU; i += 256) sw[i] = w_out[i];
    __syncthreads();

    int d = blockIdx.x * 32 + lane;
    float vh = 0.f, vm = 0.f;
#pragma unroll 8
    for (int k = 0; k < 64; k++) {
        int u = warp * 64 + k;
        float w = sw[u];
        vh = fmaf(W_h[u * D2H + d], w, vh);
        vm = fmaf(W_m[u * D2H + d], w, vm);
    }
    ph[warp][lane] = vh;
    pm[warp][lane] = vm;
    __syncthreads();

    if (warp == 0) {
        float a = 0.f;
#pragma unroll
        for (int w = 0; w < 8; w++) a += ph[w][lane];
        g_v[blockIdx.x * 32 + lane] = a;
    } else if (warp == 1) {
        float a = 0.f;
#pragma unroll
        for (int w = 0; w < 8; w++) a += pm[w][lane];
        g_v[D2H + blockIdx.x * 32 + lane] = a;
    } else if (blockIdx.x == 0 && warp == 2) {
        float ch = 0.f, cm = 0.f;
        for (int u = lane; u < UU; u += 32) {
            ch = fmaf(b_h[u], sw[u], ch);
            cm = fmaf(b_m[u], sw[u], cm);
        }
#pragma unroll
        for (int o = 16; o > 0; o >>= 1) {
            ch += __shfl_down_sync(0xffffffffu, ch, o);
            cm += __shfl_down_sync(0xffffffffu, cm, o);
        }
        if (lane == 0) {
            g_c[0] = ch + b_out[0];
            g_c[1] = cm;
        }
    }
}

// ---------------------------------------------------------------------------
// Kernel 2: dot products, two rows per warp -> 16 outstanding float4/lane.
//   sH[r] = x[r,:].v_h + c_h(+b_out) ;  sM[r] = x[r,:].v_m + c_m
// 256 threads = 8 warps = 16 rows per block. Grid: 1024 blocks.
// ---------------------------------------------------------------------------
__global__ void dots_kernel(const float* __restrict__ x) {
    __shared__ float4 sv[2 * D2H / 4];   // 8 KB: v_h then v_m as float4
    int tid = threadIdx.x;
    const float4* gv4 = (const float4*)g_v;
    for (int i = tid; i < 2 * D2H / 4; i += 256) sv[i] = gv4[i];
    __syncthreads();

    int warp = tid >> 5, lane = tid & 31;
    int row0 = (blockIdx.x * 8 + warp) * 2;

    const float4* xa = (const float4*)(x + (size_t)row0 * D2H);
    const float4* xb = xa + (D2H / 4);
    float ah0 = 0.f, am0 = 0.f, ah1 = 0.f, am1 = 0.f;
#pragma unroll
    for (int k = 0; k < 8; k++) {
        int i = k * 32 + lane;           // 256 float4 per row, coalesced
        float4 va = xa[i];
        float4 vb = xb[i];
        float4 h  = sv[i];
        float4 m  = sv[256 + i];
        ah0 = fmaf(va.x, h.x, fmaf(va.y, h.y, fmaf(va.z, h.z, fmaf(va.w, h.w, ah0))));
        am0 = fmaf(va.x, m.x, fmaf(va.y, m.y, fmaf(va.z, m.z, fmaf(va.w, m.w, am0))));
        ah1 = fmaf(vb.x, h.x, fmaf(vb.y, h.y, fmaf(vb.z, h.z, fmaf(vb.w, h.w, ah1))));
        am1 = fmaf(vb.x, m.x, fmaf(vb.y, m.y, fmaf(vb.z, m.z, fmaf(vb.w, m.w, am1))));
    }
#pragma unroll
    for (int o = 16; o > 0; o >>= 1) {
        ah0 += __shfl_down_sync(0xffffffffu, ah0, o);
        am0 += __shfl_down_sync(0xffffffffu, am0, o);
        ah1 += __shfl_down_sync(0xffffffffu, ah1, o);
        am1 += __shfl_down_sync(0xffffffffu, am1, o);
    }
    if (lane == 0) {
        float ch = g_c[0], cm = g_c[1];
        g_sH[row0]     = ah0 + ch;
        g_sM[row0]     = am0 + cm;
        g_sH[row0 + 1] = ah1 + ch;
        g_sM[row0 + 1] = am1 + cm;
    }
}

// ---------------------------------------------------------------------------
// Kernel 3: broadcast-add to the [B,N,N] output.
//   out[b,i,j] = sH[b*N+i] + sM[b*N+j]
// 8 output rows per block (8 | 1024 so same batch); each thread holds one
// float4 of sM in registers and writes it into 8 rows.
// Grid: 2048 blocks x 256 threads.
// ---------------------------------------------------------------------------
__global__ void bcast_kernel(float* __restrict__ out) {
    int bi0 = blockIdx.x * 8;            // first of 8 consecutive (b,i) rows
    int b   = bi0 >> 10;                 // N = 1024
    const float4* m4 = (const float4*)g_sM + b * (NN / 4);
    float4 m = m4[threadIdx.x];

    float s[8];
#pragma unroll
    for (int r = 0; r < 8; r++) s[r] = g_sH[bi0 + r];

    float4* o4 = (float4*)out + (size_t)bi0 * (NN / 4) + threadIdx.x;
#pragma unroll
    for (int r = 0; r < 8; r++) {
        o4[r * (NN / 4)] = make_float4(s[r] + m.x, s[r] + m.y,
                                       s[r] + m.z, s[r] + m.w);
    }
}

// ---------------------------------------------------------------------------
extern "C" void kernel_launch(void* const* d_in, const int* in_sizes, int n_in,
                              void* d_out, int out_size) {
    const float* x     = (const float*)d_in[0];
    const float* W_h   = (const float*)d_in[1];
    const float* b_h   = (const float*)d_in[2];
    const float* W_m   = (const float*)d_in[3];
    const float* b_m   = (const float*)d_in[4];
    const float* w_out = (const float*)d_in[5];
    const float* b_out = (const float*)d_in[6];
    float* out = (float*)d_out;

    fold_kernel<<<32, 256>>>(W_h, b_h, W_m, b_m, w_out, b_out);
    dots_kernel<<<BN / 16, 256>>>(x);
    bcast_kernel<<<BN / 8, 256>>>(out);
}

// round 14
// speedup vs baseline: 1.7557x; 1.3813x over previous
#include <cuda_runtime.h>

// Problem constants (fixed shapes per reference)
#define BB   16
#define NN   1024
#define D2H  1024
#define UU   512
#define BN   (BB * NN)      // 16384 rows

#define FCH     4           // fold u-chunks (UU/FCH = 128 u per chunk)
#define GRID2   512         // fused kernel grid — MUST be all-resident
#define ROWS_PB 32          // rows per fused block (512*32 = 16384)

// Scratch (device globals; no allocation allowed)
__device__ float    g_part[FCH * 2 * D2H];  // partial v_h/v_m per u-chunk (32 KB)
__device__ float    g_c[2];                 // c_h + b_out, c_m
__device__ float    g_sM[BN];               // modifier scores (cross-block)
__device__ unsigned g_sync;                 // grid barrier counter

// ---------------------------------------------------------------------------
// Kernel 1: partial fold, wide. Grid 128 = 4 u-chunks x 32 d-groups, 256 thr.
// Block (uc,dg): d in [dg*32, dg*32+32) (lane), u in [uc*128, uc*128+128)
// (warp*16 each). 16+16 coalesced loads/thread -> ~3us for 4 MB.
// Also zeroes the grid-sync counter (graph-replay idempotent) and computes
// the bias constants.
// ---------------------------------------------------------------------------
__global__ void fold_part_kernel(const float* __restrict__ W_h,
                                 const float* __restrict__ b_h,
                                 const float* __restrict__ W_m,
                                 const float* __restrict__ b_m,
                                 const float* __restrict__ w_out,
                                 const float* __restrict__ b_out) {
    __shared__ float sw[128];
    __shared__ float ph[8][32], pm[8][32];
    int tid = threadIdx.x, warp = tid >> 5, lane = tid & 31;
    int uc = blockIdx.x >> 5;            // u-chunk   0..3
    int dg = blockIdx.x & 31;            // d-group   0..31
    int u0 = uc * 128;

    if (tid < 128) sw[tid] = w_out[u0 + tid];
    if (blockIdx.x == 0 && tid == 0) g_sync = 0;   // reset barrier
    __syncthreads();

    int d = dg * 32 + lane;
    float vh = 0.f, vm = 0.f;
#pragma unroll
    for (int k = 0; k < 16; k++) {
        int u = u0 + warp * 16 + k;
        float w = sw[warp * 16 + k];
        vh = fmaf(W_h[u * D2H + d], w, vh);
        vm = fmaf(W_m[u * D2H + d], w, vm);
    }
    ph[warp][lane] = vh;
    pm[warp][lane] = vm;
    __syncthreads();

    if (warp == 0) {
        float a = 0.f;
#pragma unroll
        for (int w = 0; w < 8; w++) a += ph[w][lane];
        g_part[uc * 2 * D2H + d] = a;
    } else if (warp == 1) {
        float a = 0.f;
#pragma unroll
        for (int w = 0; w < 8; w++) a += pm[w][lane];
        g_part[uc * 2 * D2H + D2H + d] = a;
    } else if (blockIdx.x == 0 && warp == 2) {
        float ch = 0.f, cm = 0.f;
        for (int u = lane; u < UU; u += 32) {
            float w = w_out[u];
            ch = fmaf(b_h[u], w, ch);
            cm = fmaf(b_m[u], w, cm);
        }
#pragma unroll
        for (int o = 16; o > 0; o >>= 1) {
            ch += __shfl_down_sync(0xffffffffu, ch, o);
            cm += __shfl_down_sync(0xffffffffu, cm, o);
        }
        if (lane == 0) {
            g_c[0] = ch + b_out[0];
            g_c[1] = cm;
        }
    }
}

// ---------------------------------------------------------------------------
// Kernel 2: persistent fused reduce + dots + grid-sync + bcast.
// Grid 512 x 256, __launch_bounds__(256,4): 512 <= 148*4 = 592 so ALL blocks
// are resident in wave 1 -> the single grid barrier cannot deadlock and the
// two phases each run full-chip (no rolling serialization, unlike the
// per-batch-spin version).
//  Phase 0: reduce 4-chunk partials into smem sv (v_h|v_m).
//  Phase A: dots for 32 rows (4/warp, 32 outstanding float4 loads per lane);
//           sH -> smem, sM -> global (released via threadfence).
//  sync:    atomicAdd + spin until all 512 arrived.
//  Phase B: out[b,i,j] = sH[i] + sM[b,j], 32 rows, streaming stores.
// ---------------------------------------------------------------------------
__global__ void __launch_bounds__(256, 4)
fused_kernel(const float* __restrict__ x, float* __restrict__ out) {
    __shared__ float4 sv[2 * D2H / 4];   // 8 KB: v_h then v_m
    __shared__ float  ssH[ROWS_PB];
    int tid = threadIdx.x, warp = tid >> 5, lane = tid & 31;

    // Phase 0: reduce partials (g_part stays in L2: 32 KB)
    const float4* gp4 = (const float4*)g_part;
#pragma unroll
    for (int i = tid; i < 512; i += 256) {
        float4 a = gp4[i], b = gp4[512 + i], c = gp4[1024 + i], d = gp4[1536 + i];
        sv[i] = make_float4(a.x + b.x + c.x + d.x, a.y + b.y + c.y + d.y,
                            a.z + b.z + c.z + d.z, a.w + b.w + c.w + d.w);
    }
    __syncthreads();

    // Phase A: dots, 4 rows per warp
    int row0 = blockIdx.x * ROWS_PB + warp * 4;
    const float4* xr = (const float4*)(x + (size_t)row0 * D2H);
    float ah[4] = {0,0,0,0}, am[4] = {0,0,0,0};
#pragma unroll
    for (int k = 0; k < 8; k++) {
        int i = k * 32 + lane;           // 256 float4 per row, coalesced
        float4 h = sv[i], m = sv[256 + i];
#pragma unroll
        for (int r = 0; r < 4; r++) {
            float4 v = xr[r * (D2H / 4) + i];
            ah[r] = fmaf(v.x, h.x, fmaf(v.y, h.y, fmaf(v.z, h.z, fmaf(v.w, h.w, ah[r]))));
            am[r] = fmaf(v.x, m.x, fmaf(v.y, m.y, fmaf(v.z, m.z, fmaf(v.w, m.w, am[r]))));
        }
    }
#pragma unroll
    for (int o = 16; o > 0; o >>= 1) {
#pragma unroll
        for (int r = 0; r < 4; r++) {
            ah[r] += __shfl_down_sync(0xffffffffu, ah[r], o);
            am[r] += __shfl_down_sync(0xffffffffu, am[r], o);
        }
    }
    if (lane == 0) {
        float ch = g_c[0], cm = g_c[1];
#pragma unroll
        for (int r = 0; r < 4; r++) {
            ssH[warp * 4 + r] = ah[r] + ch;   // block-local
            g_sM[row0 + r]    = am[r] + cm;   // cross-block
        }
        __threadfence();                      // release sM
    }
    __syncthreads();

    // Grid barrier (all 512 blocks resident -> safe)
    if (tid == 0) {
        atomicAdd(&g_sync, 1u);
        volatile unsigned* p = &g_sync;
        while (*p < GRID2) __nanosleep(32);
    }
    __syncthreads();
    __threadfence();                          // acquire published sM

    // Phase B: broadcast-add this block's 32 rows (all same batch: 32|1024)
    int bi0 = blockIdx.x * ROWS_PB;
    int b   = bi0 >> 10;
    const float4* m4 = (const float4*)g_sM + b * (NN / 4);
    float4 m = m4[tid];

    float4* o4 = (float4*)out + (size_t)bi0 * (NN / 4) + tid;
#pragma unroll 4
    for (int r = 0; r < ROWS_PB; r++) {
        float s = ssH[r];
        __stcs(&o4[r * (NN / 4)],
               make_float4(s + m.x, s + m.y, s + m.z, s + m.w));
    }
}

// ---------------------------------------------------------------------------
extern "C" void kernel_launch(void* const* d_in, const int* in_sizes, int n_in,
                              void* d_out, int out_size) {
    const float* x     = (const float*)d_in[0];
    const float* W_h   = (const float*)d_in[1];
    const float* b_h   = (const float*)d_in[2];
    const float* W_m   = (const float*)d_in[3];
    const float* b_m   = (const float*)d_in[4];
    const float* w_out = (const float*)d_in[5];
    const float* b_out = (const float*)d_in[6];
    float* out = (float*)d_out;

    fold_part_kernel<<<32 * FCH, 256>>>(W_h, b_h, W_m, b_m, w_out, b_out);
    fused_kernel<<<GRID2, 256>>>(x, out);
}